// round 12
// baseline (speedup 1.0000x reference)
#include <cuda_runtime.h>
#include <cuda_fp16.h>
#include <math.h>
#include <cstdint>

#define Bb 64
#define Tt 50000
#define Cc 4
#define MS 4
#define Dd 160
#define PP 25
#define KE 25
#define KB 9
#define KP 9
#define LL 2000
#define TILE 500
#define NT (Tt / TILE)          // 100
#define RPT (TILE / PP)         // 20 rows per tile
#define HSIZE (Bb * LL * Dd)
#define KK 100
#define NWIN 536
#define NS0 512
#define XST 120                 // sX stride in halves (k' pad 112 + 8)
#define XROWS 32

// precomputed W B-fragments (fp16, k-permuted k' = p*4+o): [kc 7][nn 20][lane 32][rb 2]
#define NKC 7
#define NNC 20
#define BFRAG_U32 (NKC * NNC * 64)
__device__ unsigned g_bfrag[BFRAG_U32];

typedef unsigned long long ull;

__device__ __forceinline__ float gelu_exact(float v) {
    return 0.5f * v * (1.0f + erff(v * 0.70710678118654752f));
}
__device__ __forceinline__ float softplus_f(float v) {
    return fmaxf(v, 0.0f) + log1pf(expf(-fabsf(v)));
}
__device__ __forceinline__ ull ffma2(ull a, ull b, ull c) {
    ull d;
    asm("fma.rn.f32x2 %0, %1, %2, %3;" : "=l"(d) : "l"(a), "l"(b), "l"(c));
    return d;
}
__device__ __forceinline__ ull mul2(ull a, ull b) {
    ull d;
    asm("mul.rn.f32x2 %0, %1, %2;" : "=l"(d) : "l"(a), "l"(b));
    return d;
}
__device__ __forceinline__ ull pack2(float x, float y) {
    ull d;
    asm("mov.b64 %0, {%1, %2};" : "=l"(d) : "f"(x), "f"(y));
    return d;
}
union F4U { float4 v; ull u[2]; };
union UF2 { ull u; float2 f; };
union H4U { __half h[4]; ull u; };

#define ABS2MASK 0x7FFFFFFF7FFFFFFFULL
#define NEG1P    0xBF800000BF800000ULL
#define C09P     0x3F6666663F666666ULL
#define C06P     0x3F19999A3F19999AULL
#define C02P     0x3E4CCCCD3E4CCCCDULL

__device__ __forceinline__ unsigned packh2(float a, float b) {
    __half2 t = __floats2half2_rn(a, b);
    return *reinterpret_cast<unsigned*>(&t);
}

__device__ __forceinline__ void hmma16816(
    float& c0, float& c1, float& c2, float& c3,
    unsigned a0, unsigned a1, unsigned a2, unsigned a3,
    unsigned b0, unsigned b1)
{
    asm volatile(
        "mma.sync.aligned.m16n8k16.row.col.f32.f16.f16.f32 "
        "{%0,%1,%2,%3}, {%4,%5,%6,%7}, {%8,%9}, {%0,%1,%2,%3};"
        : "+f"(c0), "+f"(c1), "+f"(c2), "+f"(c3)
        : "r"(a0), "r"(a1), "r"(a2), "r"(a3), "r"(b0), "r"(b1));
}

// ---------------------------------------------------------------------------
// Kernel W: precompute fp16 B-fragments of wproj, with K permuted (k' = p*4+o)
//   logical k' -> original k = (k'&3)*25 + (k'>>2)
// ---------------------------------------------------------------------------
__global__ void kernelW(const float* __restrict__ wproj) {
    int i = blockIdx.x * 256 + threadIdx.x;
    if (i >= BFRAG_U32) return;
    int kc  = i / (NNC * 64);
    int r2  = i % (NNC * 64);
    int nn  = r2 / 64;
    int q   = r2 % 64;
    int lane = q >> 1, rb = q & 1;
    int d  = nn * 8 + (lane >> 2);
    int kp = kc * 16 + (lane & 3) * 2 + rb * 8;
    float w0 = (kp < KK)     ? wproj[d * KK + (kp & 3) * 25 + (kp >> 2)] : 0.f;
    float w1 = (kp + 1 < KK) ? wproj[d * KK + ((kp + 1) & 3) * 25 + ((kp + 1) >> 2)] : 0.f;
    g_bfrag[i] = packh2(w0, w1);
}

// ---------------------------------------------------------------------------
// Fused kernel, TILE=500, 3 blocks/SM.
// Dynamic smem layout (overlaid):
//   [0 .. 8576)      sxr2 [2][536] ull (raw masked x pairs)
//   [8576 .. 17152)  sdx2 [2][536] ull (|dx| pairs)
//   [17152 .. 25728) sabs [2][536] ull (|x| pairs)
//                    -> all reused as sB [8960] u32 (0..35840) after phase B
//   [35840 .. 44032) sS02 [2][512] ull  -> after HMMA reused as scratch
//   [44032 .. 51712) sXh [32][120] half (k'-major: pos-major, o contiguous)
//   [51712 .. 59392) sXl [32][120] half
// scratch (pass-combine): [35840 .. 56320) floats [4 nq][32 lanes][40]
// ---------------------------------------------------------------------------
#define OFF_SDX  8576
#define OFF_SAB  17152
#define OFF_SS0  35840
#define OFF_XH   44032
#define OFF_XL   51712
#define OFF_SCR  35840
#define DYN_SMEM 59392

__global__ __launch_bounds__(256, 3) void kernelF(
    const float* __restrict__ X, const float* __restrict__ Mv,
    const float* __restrict__ w_env, const float* __restrict__ w_burst,
    const float* __restrict__ syn, const float* __restrict__ w_dw,
    const float* __restrict__ w_pw, const float* __restrict__ gamma,
    const float* __restrict__ beta, float* __restrict__ out)
{
    extern __shared__ __align__(16) char dsm[];
    ull* sxr2 = (ull*)dsm;                       // [2][536] raw
    ull* sdx2 = (ull*)(dsm + OFF_SDX);           // [2][536] |dx|
    ull* sabs = (ull*)(dsm + OFF_SAB);           // [2][536] |x|
    unsigned* sB = (unsigned*)dsm;               // overlays after phase B
    ull* sS02 = (ull*)(dsm + OFF_SS0);           // [2][512]
    __half* sXh = (__half*)(dsm + OFF_XH);       // [32][120]
    __half* sXl = (__half*)(dsm + OFF_XL);       // [32][120]

    __shared__ uchar4 smask[TILE];
    __shared__ unsigned char smt[TILE];
    __shared__ float sW[MS][Cc];
    __shared__ float sPW[MS][MS];
    __shared__ ull swe2[2][KE], swb2[2][KB], swd2[2][KP], sWsyn2[2][MS];
    __shared__ float sG[Dd], sBt[Dd];
    __shared__ float sSum[4][XROWS], sSq[4][XROWS];
    __shared__ float sMu[RPT], sRs[RPT];

    const int tid  = threadIdx.x;
    const int lane = tid & 31;
    const int wid  = tid >> 5;
    const int tile = blockIdx.x;
    const int b    = blockIdx.y;
    const int t0   = tile * TILE;
    const int Row0 = b * LL + tile * RPT;

    // ---- small weights ----
    if (tid < MS) {
        float v0 = softplus_f(syn[tid * Cc + 0]);
        float v1 = softplus_f(syn[tid * Cc + 1]);
        float v2 = softplus_f(syn[tid * Cc + 2]);
        float v3 = softplus_f(syn[tid * Cc + 3]);
        float s  = fmaxf(v0 + v1 + v2 + v3, 1e-6f);
        float inv = 1.0f / s;
        sW[tid][0] = v0 * inv; sW[tid][1] = v1 * inv;
        sW[tid][2] = v2 * inv; sW[tid][3] = v3 * inv;
    }
    if (tid >= 32 && tid < 32 + MS * MS) {
        int i = tid - 32;
        sPW[i / MS][i % MS] = w_pw[i];
    }
    for (int i = tid; i < Dd; i += 256) { sG[i] = gamma[i]; sBt[i] = beta[i]; }

    // ---- pass 1: raw masked x pairs + mask bytes ----
    const float4* X4 = (const float4*)(X + (size_t)b * Tt * Cc);
    const float4* M4 = (const float4*)(Mv + (size_t)b * Tt * Cc);
    for (int i = tid; i < TILE + 33; i += 256) {
        int t = t0 - 16 + i;
        float x0 = 0.f, x1 = 0.f, x2 = 0.f, x3 = 0.f;
        uchar4 mk = {0, 0, 0, 0};
        if (t >= 0 && t < Tt) {
            float4 a = X4[t], m = M4[t];
            x0 = a.x * m.x; x1 = a.y * m.y; x2 = a.z * m.z; x3 = a.w * m.w;
            mk.x = (m.x > 0.f); mk.y = (m.y > 0.f); mk.z = (m.z > 0.f); mk.w = (m.w > 0.f);
        }
        sxr2[i] = pack2(x0, x1);
        sxr2[NWIN + i] = pack2(x2, x3);
        int j = i - 16;
        if (j >= 0 && j < TILE) smask[j] = mk;
    }
    __syncthreads();

    // ---- weight pair packing + dx/abs pass + zero sX ----
    if (tid < 2 * KE) {
        int cp = tid / KE, k = tid - cp * KE;
        swe2[cp][k] = pack2(w_env[(2 * cp) * KE + k], w_env[(2 * cp + 1) * KE + k]);
    } else if (tid >= 64 && tid < 64 + 2 * KB) {
        int i = tid - 64, cp = i / KB, k = i - cp * KB;
        swb2[cp][k] = pack2(w_burst[(2 * cp) * KB + k], w_burst[(2 * cp + 1) * KB + k]);
    } else if (tid >= 96 && tid < 96 + 2 * KP) {
        int i = tid - 96, p2 = i / KP, k = i - p2 * KP;
        swd2[p2][k] = pack2(w_dw[(2 * p2) * KP + k], w_dw[(2 * p2 + 1) * KP + k]);
    } else if (tid >= 128 && tid < 128 + 2 * MS) {
        int i = tid - 128, cp = i / MS, m = i - cp * MS;
        sWsyn2[cp][m] = pack2(sW[m][2 * cp], sW[m][2 * cp + 1]);
    }
    for (int i = tid; i < XROWS * XST / 2; i += 256) {
        ((unsigned*)sXh)[i] = 0u;
        ((unsigned*)sXl)[i] = 0u;
    }
    for (int i = tid; i < TILE + 33; i += 256) {
        int tg = t0 - 16 + i;
        bool v = (tg >= 1) && (tg < Tt) && (i >= 1);
        ull r0 = sxr2[i];
        ull r1 = sxr2[NWIN + i];
        ull d0 = 0, d1 = 0;
        if (v) {
            d0 = ffma2(sxr2[i - 1], NEG1P, r0) & ABS2MASK;
            d1 = ffma2(sxr2[NWIN + i - 1], NEG1P, r1) & ABS2MASK;
        }
        sdx2[i] = d0;
        sdx2[NWIN + i] = d1;
        sabs[i] = r0 & ABS2MASK;
        sabs[NWIN + i] = r1 & ABS2MASK;
    }
    __syncthreads();

    // ---- phase B: rolling-window env/burst/xm -> S0 pairs (no ANDs) ----
    if (tid < 254) {
        const int j0 = tid * 2;
        ull accm[MS][2];
        #pragma unroll
        for (int m = 0; m < MS; m++) { accm[m][0] = 0ULL; accm[m][1] = 0ULL; }

        #pragma unroll
        for (int cp = 0; cp < 2; cp++) {
            const ull* xa = sabs + cp * NWIN;
            const ull* dx = sdx2 + cp * NWIN;
            ull env0 = 0ULL, env1 = 0ULL;
            #pragma unroll
            for (int u = 0; u < 13; u++) {
                F4U v; v.v = *(const float4*)&xa[j0 + 2 * u];
                ull p0 = v.u[0];
                ull p1 = v.u[1];
                const int k0 = 2 * u;
                if (k0 <= 24)     env0 = ffma2(p0, swe2[cp][k0], env0);
                if (k0 + 1 <= 24) env0 = ffma2(p1, swe2[cp][k0 + 1], env0);
                if (k0 >= 1)      env1 = ffma2(p0, swe2[cp][k0 - 1], env1);
                if (k0 <= 24)     env1 = ffma2(p1, swe2[cp][k0], env1);
            }
            F4U vr; vr.v = *(const float4*)&sxr2[cp * NWIN + j0 + 12];
            ull xraw0 = vr.u[0], xraw1 = vr.u[1];
            ull bur0 = 0ULL, bur1 = 0ULL;
            #pragma unroll
            for (int u = 0; u < 5; u++) {
                F4U v; v.v = *(const float4*)&dx[j0 + 8 + 2 * u];
                const int k0 = 2 * u;
                if (k0 <= 8)     bur0 = ffma2(v.u[0], swb2[cp][k0], bur0);
                if (k0 + 1 <= 8) bur0 = ffma2(v.u[1], swb2[cp][k0 + 1], bur0);
                if (k0 >= 1)     bur1 = ffma2(v.u[0], swb2[cp][k0 - 1], bur1);
                if (k0 <= 8)     bur1 = ffma2(v.u[1], swb2[cp][k0], bur1);
            }
            ull xm0 = ffma2(env0, C09P, ffma2(bur0, C06P, mul2(xraw0, C02P)));
            ull xm1 = ffma2(env1, C09P, ffma2(bur1, C06P, mul2(xraw1, C02P)));
            #pragma unroll
            for (int m = 0; m < MS; m++) {
                ull w = sWsyn2[cp][m];
                accm[m][0] = ffma2(xm0, w, accm[m][0]);
                accm[m][1] = ffma2(xm1, w, accm[m][1]);
            }
        }
        #pragma unroll
        for (int p = 0; p < 2; p++) {
            int j  = j0 + p;
            int tp = t0 - 4 + j;
            bool valid = (tp >= 0 && tp < Tt);
            float s0[MS];
            #pragma unroll
            for (int m = 0; m < MS; m++) {
                UF2 u; u.u = accm[m][p];
                s0[m] = valid ? (u.f.x + u.f.y) : 0.f;
            }
            sS02[j] = pack2(s0[0], s0[1]);
            sS02[NS0 + j] = pack2(s0[2], s0[3]);
        }
    }
    __syncthreads();
    // sxr2/sdx2/sabs dead -> sB overlay free

    // ---- B-fragment copy into overlay ----
    {
        const uint4* src = (const uint4*)g_bfrag;
        uint4* dst = (uint4*)sB;
        for (int i = tid; i < BFRAG_U32 / 4; i += 256) dst[i] = src[i];
    }

    // ---- phase C: rolling dwconv9+gelu, pointwise+gelu, write sX (k'-packed) ----
    if (tid < 250) {
        const int i0 = tid * 2;
        float S1[2][MS];
        #pragma unroll
        for (int p2 = 0; p2 < 2; p2++) {
            const ull* s0p = sS02 + p2 * NS0;
            ull a0 = 0ULL, a1 = 0ULL;
            #pragma unroll
            for (int u = 0; u < 5; u++) {
                F4U v; v.v = *(const float4*)&s0p[i0 + 2 * u];
                const int k0 = 2 * u;
                if (k0 <= 8)     a0 = ffma2(v.u[0], swd2[p2][k0], a0);
                if (k0 + 1 <= 8) a0 = ffma2(v.u[1], swd2[p2][k0 + 1], a0);
                if (k0 >= 1)     a1 = ffma2(v.u[0], swd2[p2][k0 - 1], a1);
                if (k0 <= 8)     a1 = ffma2(v.u[1], swd2[p2][k0], a1);
            }
            UF2 u0, u1; u0.u = a0; u1.u = a1;
            S1[0][2 * p2]     = gelu_exact(u0.f.x);
            S1[0][2 * p2 + 1] = gelu_exact(u0.f.y);
            S1[1][2 * p2]     = gelu_exact(u1.f.x);
            S1[1][2 * p2 + 1] = gelu_exact(u1.f.y);
        }
        #pragma unroll
        for (int pos = 0; pos < 2; pos++) {
            int i = i0 + pos;
            uchar4 mk = smask[i];
            float mf0 = (float)mk.x, mf1 = (float)mk.y, mf2 = (float)mk.z, mf3 = (float)mk.w;
            int l = i / PP, p = i - l * PP;
            float smsum = 0.f;
            H4U Hh, Hl;
            #pragma unroll
            for (int o = 0; o < MS; o++) {
                float a  = sPW[o][0] * S1[pos][0] + sPW[o][1] * S1[pos][1]
                         + sPW[o][2] * S1[pos][2] + sPW[o][3] * S1[pos][3];
                float s2 = gelu_exact(a);
                float sm = sW[o][0] * mf0 + sW[o][1] * mf1 + sW[o][2] * mf2 + sW[o][3] * mf3;
                sm = fminf(fmaxf(sm, 0.f), 1.f);
                smsum += sm;
                float v = s2 * sm;
                __half h = __float2half_rn(v);
                Hh.h[o] = h;
                Hl.h[o] = __float2half_rn(v - __half2float(h));
            }
            // k' = p*4 + o  -> one ull covers o=0..3 at ull index l*30 + p
            ((ull*)sXh)[l * (XST / 4) + p] = Hh.u;
            ((ull*)sXl)[l * (XST / 4) + p] = Hl.u;
            smt[i] = (smsum > 0.f) ? 1 : 0;
        }
    }
    __syncthreads();

    // ---- m_patch ----
    if (tid < RPT) {
        int s = 0;
        #pragma unroll
        for (int p = 0; p < PP; p++) s += smt[tid * PP + p];
        out[(size_t)HSIZE + Row0 + tid] = (s >= 3) ? 1.f : 0.f;
    }

    // ---- HMMA mainloop: 8 warps = 2 pass x 4 n-quarter, both row-groups ----
    const int pss = wid >> 2;          // 0 = hi, 1 = lo
    const int nq  = wid & 3;           // n-quarter (5 nn chunks each)
    const int r0  = lane >> 2;

    float acc[2][5][4];
    #pragma unroll
    for (int g = 0; g < 2; g++)
        #pragma unroll
        for (int n = 0; n < 5; n++)
            #pragma unroll
            for (int j = 0; j < 4; j++) acc[g][n][j] = 0.f;

    {
        const __half* sX = pss ? sXl : sXh;
        #pragma unroll
        for (int kc = 0; kc < NKC; kc++) {
            int c0 = kc * 16 + (lane & 3) * 2;
            unsigned a00 = *(const unsigned*)&sX[r0 * XST + c0];
            unsigned a01 = *(const unsigned*)&sX[(r0 + 8) * XST + c0];
            unsigned a02 = *(const unsigned*)&sX[r0 * XST + c0 + 8];
            unsigned a03 = *(const unsigned*)&sX[(r0 + 8) * XST + c0 + 8];
            unsigned a10 = *(const unsigned*)&sX[(r0 + 16) * XST + c0];
            unsigned a11 = *(const unsigned*)&sX[(r0 + 24) * XST + c0];
            unsigned a12 = *(const unsigned*)&sX[(r0 + 16) * XST + c0 + 8];
            unsigned a13 = *(const unsigned*)&sX[(r0 + 24) * XST + c0 + 8];
            #pragma unroll
            for (int n = 0; n < 5; n++) {
                int nn = nq * 5 + n;
                uint2 bf = *(const uint2*)&sB[(kc * NNC + nn) * 64 + lane * 2];
                hmma16816(acc[0][n][0], acc[0][n][1], acc[0][n][2], acc[0][n][3],
                          a00, a01, a02, a03, bf.x, bf.y);
                hmma16816(acc[1][n][0], acc[1][n][1], acc[1][n][2], acc[1][n][3],
                          a10, a11, a12, a13, bf.x, bf.y);
            }
        }
    }
    __syncthreads();   // sX/sS02 dead; scratch region safe

    float* scr = (float*)(dsm + OFF_SCR);   // [4 nq][32 lanes][40]
    if (pss == 1) {
        float* d = scr + (nq * 32 + lane) * 40;
        #pragma unroll
        for (int g = 0; g < 2; g++)
            #pragma unroll
            for (int n = 0; n < 5; n++)
                *(float4*)&d[(g * 5 + n) * 4] =
                    make_float4(acc[g][n][0], acc[g][n][1], acc[g][n][2], acc[g][n][3]);
    }
    __syncthreads();
    if (pss == 0) {
        const float* d = scr + (nq * 32 + lane) * 40;
        #pragma unroll
        for (int g = 0; g < 2; g++)
            #pragma unroll
            for (int n = 0; n < 5; n++) {
                float4 v = *(const float4*)&d[(g * 5 + n) * 4];
                acc[g][n][0] += v.x; acc[g][n][1] += v.y;
                acc[g][n][2] += v.z; acc[g][n][3] += v.w;
            }
        // ---- LN partial moments: 4 row-sets per warp, quad reduce ----
        float s0 = 0.f, q0 = 0.f, s1 = 0.f, q1 = 0.f;
        float s2 = 0.f, q2 = 0.f, s3 = 0.f, q3 = 0.f;
        #pragma unroll
        for (int n = 0; n < 5; n++) {
            s0 += acc[0][n][0] + acc[0][n][1];
            q0 += acc[0][n][0] * acc[0][n][0] + acc[0][n][1] * acc[0][n][1];
            s1 += acc[0][n][2] + acc[0][n][3];
            q1 += acc[0][n][2] * acc[0][n][2] + acc[0][n][3] * acc[0][n][3];
            s2 += acc[1][n][0] + acc[1][n][1];
            q2 += acc[1][n][0] * acc[1][n][0] + acc[1][n][1] * acc[1][n][1];
            s3 += acc[1][n][2] + acc[1][n][3];
            q3 += acc[1][n][2] * acc[1][n][2] + acc[1][n][3] * acc[1][n][3];
        }
        #pragma unroll
        for (int off = 1; off <= 2; off <<= 1) {
            s0 += __shfl_xor_sync(0xFFFFFFFFu, s0, off);
            q0 += __shfl_xor_sync(0xFFFFFFFFu, q0, off);
            s1 += __shfl_xor_sync(0xFFFFFFFFu, s1, off);
            q1 += __shfl_xor_sync(0xFFFFFFFFu, q1, off);
            s2 += __shfl_xor_sync(0xFFFFFFFFu, s2, off);
            q2 += __shfl_xor_sync(0xFFFFFFFFu, q2, off);
            s3 += __shfl_xor_sync(0xFFFFFFFFu, s3, off);
            q3 += __shfl_xor_sync(0xFFFFFFFFu, q3, off);
        }
        if ((lane & 3) == 0) {
            sSum[nq][r0]      = s0; sSq[nq][r0]      = q0;
            sSum[nq][r0 + 8]  = s1; sSq[nq][r0 + 8]  = q1;
            sSum[nq][r0 + 16] = s2; sSq[nq][r0 + 16] = q2;
            sSum[nq][r0 + 24] = s3; sSq[nq][r0 + 24] = q3;
        }
    }
    __syncthreads();

    if (tid < RPT) {
        float s = sSum[0][tid] + sSum[1][tid] + sSum[2][tid] + sSum[3][tid];
        float q = sSq[0][tid] + sSq[1][tid] + sSq[2][tid] + sSq[3][tid];
        float mu  = s * (1.0f / Dd);
        float var = q * (1.0f / Dd) - mu * mu;
        sMu[tid] = mu;
        sRs[tid] = rsqrtf(var + 1e-5f);
    }
    __syncthreads();

    if (pss == 0) {
        #pragma unroll
        for (int g = 0; g < 2; g++) {
            int rA = r0 + g * 16;
            int rB = rA + 8;
            bool hasA = (rA < RPT);
            bool hasB = (rB < RPT);
            float muA = hasA ? sMu[rA] : 0.f, rsA = hasA ? sRs[rA] : 0.f;
            float muB = hasB ? sMu[rB] : 0.f, rsB = hasB ? sRs[rB] : 0.f;
            float* outA = out + (size_t)(Row0 + rA) * Dd;
            float* outB = out + (size_t)(Row0 + rB) * Dd;
            #pragma unroll
            for (int n = 0; n < 5; n++) {
                int col = (nq * 5 + n) * 8 + (lane & 3) * 2;
                float2 gm = *(const float2*)&sG[col];
                float2 bt = *(const float2*)&sBt[col];
                if (hasA) {
                    float2 v;
                    v.x = (acc[g][n][0] - muA) * rsA * gm.x + bt.x;
                    v.y = (acc[g][n][1] - muA) * rsA * gm.y + bt.y;
                    *(float2*)(outA + col) = v;
                }
                if (hasB) {
                    float2 v;
                    v.x = (acc[g][n][2] - muB) * rsB * gm.x + bt.x;
                    v.y = (acc[g][n][3] - muB) * rsB * gm.y + bt.y;
                    *(float2*)(outB + col) = v;
                }
            }
        }
    }
}

// ---------------------------------------------------------------------------
extern "C" void kernel_launch(void* const* d_in, const int* in_sizes, int n_in,
                              void* d_out, int out_size)
{
    const float* X      = (const float*)d_in[0];
    const float* M      = (const float*)d_in[1];
    const float* w_env  = (const float*)d_in[2];
    const float* w_bur  = (const float*)d_in[3];
    const float* syn    = (const float*)d_in[4];
    const float* w_dw   = (const float*)d_in[5];
    const float* w_pw   = (const float*)d_in[6];
    const float* w_proj = (const float*)d_in[7];
    const float* gamma  = (const float*)d_in[8];
    const float* beta   = (const float*)d_in[9];
    float* out = (float*)d_out;

    cudaFuncSetAttribute(kernelF, cudaFuncAttributeMaxDynamicSharedMemorySize, DYN_SMEM);

    kernelW<<<(BFRAG_U32 + 255) / 256, 256>>>(w_proj);
    dim3 gF(NT, Bb);
    kernelF<<<gF, 256, DYN_SMEM>>>(X, M, w_env, w_bur, syn, w_dw, w_pw,
                                   gamma, beta, out);
}

// round 15
// speedup vs baseline: 1.2831x; 1.2831x over previous
#include <cuda_runtime.h>
#include <cuda_fp16.h>
#include <math.h>
#include <cstdint>

#define Bb 64
#define Tt 50000
#define Cc 4
#define MS 4
#define Dd 160
#define PP 25
#define KE 25
#define KB 9
#define KP 9
#define LL 2000
#define TILE 500
#define NT (Tt / TILE)          // 100
#define RPT (TILE / PP)         // 20 rows per tile
#define HSIZE (Bb * LL * Dd)
#define KK 100
#define NWIN 536
#define NS0 512
#define XST 120                 // sX stride in halves (k' pad 112 + 8)
#define XROWS 32

// precomputed W B-fragments (fp16, k-permuted k' = p*4+o): [kc 7][nn 20][lane 32][rb 2]
#define NKC 7
#define NNC 20
#define BFRAG_U32 (NKC * NNC * 64)
__device__ unsigned g_bfrag[BFRAG_U32];

typedef unsigned long long ull;

__device__ __forceinline__ float gelu_exact(float v) {
    return 0.5f * v * (1.0f + erff(v * 0.70710678118654752f));
}
__device__ __forceinline__ float softplus_f(float v) {
    return fmaxf(v, 0.0f) + log1pf(expf(-fabsf(v)));
}
__device__ __forceinline__ ull ffma2(ull a, ull b, ull c) {
    ull d;
    asm("fma.rn.f32x2 %0, %1, %2, %3;" : "=l"(d) : "l"(a), "l"(b), "l"(c));
    return d;
}
__device__ __forceinline__ ull mul2(ull a, ull b) {
    ull d;
    asm("mul.rn.f32x2 %0, %1, %2;" : "=l"(d) : "l"(a), "l"(b));
    return d;
}
__device__ __forceinline__ ull pack2(float x, float y) {
    ull d;
    asm("mov.b64 %0, {%1, %2};" : "=l"(d) : "f"(x), "f"(y));
    return d;
}
union F4U { float4 v; ull u[2]; };
union UF2 { ull u; float2 f; };
union H4U { __half h[4]; ull u; };

#define ABS2MASK 0x7FFFFFFF7FFFFFFFULL
#define NEG1P    0xBF800000BF800000ULL
#define C09P     0x3F6666663F666666ULL
#define C06P     0x3F19999A3F19999AULL
#define C02P     0x3E4CCCCD3E4CCCCDULL

__device__ __forceinline__ unsigned packh2(float a, float b) {
    __half2 t = __floats2half2_rn(a, b);
    return *reinterpret_cast<unsigned*>(&t);
}

__device__ __forceinline__ void hmma16816(
    float& c0, float& c1, float& c2, float& c3,
    unsigned a0, unsigned a1, unsigned a2, unsigned a3,
    unsigned b0, unsigned b1)
{
    asm volatile(
        "mma.sync.aligned.m16n8k16.row.col.f32.f16.f16.f32 "
        "{%0,%1,%2,%3}, {%4,%5,%6,%7}, {%8,%9}, {%0,%1,%2,%3};"
        : "+f"(c0), "+f"(c1), "+f"(c2), "+f"(c3)
        : "r"(a0), "r"(a1), "r"(a2), "r"(a3), "r"(b0), "r"(b1));
}

// ---------------------------------------------------------------------------
// Kernel W: precompute fp16 B-fragments of wproj, with K permuted (k' = p*4+o)
//   logical k' -> original k = (k'&3)*25 + (k'>>2)
// ---------------------------------------------------------------------------
__global__ void kernelW(const float* __restrict__ wproj) {
    int i = blockIdx.x * 256 + threadIdx.x;
    if (i >= BFRAG_U32) return;
    int kc  = i / (NNC * 64);
    int r2  = i % (NNC * 64);
    int nn  = r2 / 64;
    int q   = r2 % 64;
    int lane = q >> 1, rb = q & 1;
    int d  = nn * 8 + (lane >> 2);
    int kp = kc * 16 + (lane & 3) * 2 + rb * 8;
    float w0 = (kp < KK)     ? wproj[d * KK + (kp & 3) * 25 + (kp >> 2)] : 0.f;
    float w1 = (kp + 1 < KK) ? wproj[d * KK + ((kp + 1) & 3) * 25 + ((kp + 1) >> 2)] : 0.f;
    g_bfrag[i] = packh2(w0, w1);
}

// ---------------------------------------------------------------------------
// Fused kernel, TILE=500, 4 blocks/SM target.
// Dynamic smem layout:
//   [0 .. 8576)      sxr2 [2][536] ull (raw masked x pairs)
//   [8576 .. 17152)  sdx2 [2][536] ull (|dx| pairs)
//   [17152 .. 25728) sabs [2][536] ull (|x| pairs)
//   [25728 .. 33920) sS02 [2][512] ull
//   [33920 .. 41600) sXh [32][120] half
//   [41600 .. 49280) sXl [32][120] half
// B-fragments are read straight from gmem (L2-resident, shared by all blocks).
// ---------------------------------------------------------------------------
#define OFF_SDX  8576
#define OFF_SAB  17152
#define OFF_SS0  25728
#define OFF_XH   33920
#define OFF_XL   41600
#define DYN_SMEM 49280

__global__ __launch_bounds__(256, 4) void kernelF(
    const float* __restrict__ X, const float* __restrict__ Mv,
    const float* __restrict__ w_env, const float* __restrict__ w_burst,
    const float* __restrict__ syn, const float* __restrict__ w_dw,
    const float* __restrict__ w_pw, const float* __restrict__ gamma,
    const float* __restrict__ beta, float* __restrict__ out)
{
    extern __shared__ __align__(16) char dsm[];
    ull* sxr2 = (ull*)dsm;                       // [2][536] raw
    ull* sdx2 = (ull*)(dsm + OFF_SDX);           // [2][536] |dx|
    ull* sabs = (ull*)(dsm + OFF_SAB);           // [2][536] |x|
    ull* sS02 = (ull*)(dsm + OFF_SS0);           // [2][512]
    __half* sXh = (__half*)(dsm + OFF_XH);       // [32][120]
    __half* sXl = (__half*)(dsm + OFF_XL);       // [32][120]

    __shared__ uchar4 smask[TILE];
    __shared__ unsigned char smt[TILE];
    __shared__ float sW[MS][Cc];
    __shared__ float sPW[MS][MS];
    __shared__ ull swe2[2][KE], swb2[2][KB], swd2[2][KP], sWsyn2[2][MS];
    __shared__ float sG[Dd], sBt[Dd];
    __shared__ float sSum[4][XROWS], sSq[4][XROWS];
    __shared__ float sMu[RPT], sRs[RPT];

    const int tid  = threadIdx.x;
    const int lane = tid & 31;
    const int wid  = tid >> 5;
    const int tile = blockIdx.x;
    const int b    = blockIdx.y;
    const int t0   = tile * TILE;
    const int Row0 = b * LL + tile * RPT;

    // ---- small weights ----
    if (tid < MS) {
        float v0 = softplus_f(syn[tid * Cc + 0]);
        float v1 = softplus_f(syn[tid * Cc + 1]);
        float v2 = softplus_f(syn[tid * Cc + 2]);
        float v3 = softplus_f(syn[tid * Cc + 3]);
        float s  = fmaxf(v0 + v1 + v2 + v3, 1e-6f);
        float inv = 1.0f / s;
        sW[tid][0] = v0 * inv; sW[tid][1] = v1 * inv;
        sW[tid][2] = v2 * inv; sW[tid][3] = v3 * inv;
    }
    if (tid >= 32 && tid < 32 + MS * MS) {
        int i = tid - 32;
        sPW[i / MS][i % MS] = w_pw[i];
    }
    for (int i = tid; i < Dd; i += 256) { sG[i] = gamma[i]; sBt[i] = beta[i]; }

    // ---- pass 1: raw masked x pairs + mask bytes ----
    const float4* X4 = (const float4*)(X + (size_t)b * Tt * Cc);
    const float4* M4 = (const float4*)(Mv + (size_t)b * Tt * Cc);
    for (int i = tid; i < TILE + 33; i += 256) {
        int t = t0 - 16 + i;
        float x0 = 0.f, x1 = 0.f, x2 = 0.f, x3 = 0.f;
        uchar4 mk = {0, 0, 0, 0};
        if (t >= 0 && t < Tt) {
            float4 a = X4[t], m = M4[t];
            x0 = a.x * m.x; x1 = a.y * m.y; x2 = a.z * m.z; x3 = a.w * m.w;
            mk.x = (m.x > 0.f); mk.y = (m.y > 0.f); mk.z = (m.z > 0.f); mk.w = (m.w > 0.f);
        }
        sxr2[i] = pack2(x0, x1);
        sxr2[NWIN + i] = pack2(x2, x3);
        int j = i - 16;
        if (j >= 0 && j < TILE) smask[j] = mk;
    }
    __syncthreads();

    // ---- weight pair packing + dx/abs pass + zero sX ----
    if (tid < 2 * KE) {
        int cp = tid / KE, k = tid - cp * KE;
        swe2[cp][k] = pack2(w_env[(2 * cp) * KE + k], w_env[(2 * cp + 1) * KE + k]);
    } else if (tid >= 64 && tid < 64 + 2 * KB) {
        int i = tid - 64, cp = i / KB, k = i - cp * KB;
        swb2[cp][k] = pack2(w_burst[(2 * cp) * KB + k], w_burst[(2 * cp + 1) * KB + k]);
    } else if (tid >= 96 && tid < 96 + 2 * KP) {
        int i = tid - 96, p2 = i / KP, k = i - p2 * KP;
        swd2[p2][k] = pack2(w_dw[(2 * p2) * KP + k], w_dw[(2 * p2 + 1) * KP + k]);
    } else if (tid >= 128 && tid < 128 + 2 * MS) {
        int i = tid - 128, cp = i / MS, m = i - cp * MS;
        sWsyn2[cp][m] = pack2(sW[m][2 * cp], sW[m][2 * cp + 1]);
    }
    for (int i = tid; i < XROWS * XST / 2; i += 256) {
        ((unsigned*)sXh)[i] = 0u;
        ((unsigned*)sXl)[i] = 0u;
    }
    for (int i = tid; i < TILE + 33; i += 256) {
        int tg = t0 - 16 + i;
        bool v = (tg >= 1) && (tg < Tt) && (i >= 1);
        ull r0 = sxr2[i];
        ull r1 = sxr2[NWIN + i];
        ull d0 = 0, d1 = 0;
        if (v) {
            d0 = ffma2(sxr2[i - 1], NEG1P, r0) & ABS2MASK;
            d1 = ffma2(sxr2[NWIN + i - 1], NEG1P, r1) & ABS2MASK;
        }
        sdx2[i] = d0;
        sdx2[NWIN + i] = d1;
        sabs[i] = r0 & ABS2MASK;
        sabs[NWIN + i] = r1 & ABS2MASK;
    }
    __syncthreads();

    // ---- phase B: rolling-window env/burst/xm -> S0 pairs ----
    if (tid < 254) {
        const int j0 = tid * 2;
        ull accm[MS][2];
        #pragma unroll
        for (int m = 0; m < MS; m++) { accm[m][0] = 0ULL; accm[m][1] = 0ULL; }

        #pragma unroll
        for (int cp = 0; cp < 2; cp++) {
            const ull* xa = sabs + cp * NWIN;
            const ull* dx = sdx2 + cp * NWIN;
            ull env0 = 0ULL, env1 = 0ULL;
            #pragma unroll
            for (int u = 0; u < 13; u++) {
                F4U v; v.v = *(const float4*)&xa[j0 + 2 * u];
                ull p0 = v.u[0];
                ull p1 = v.u[1];
                const int k0 = 2 * u;
                if (k0 <= 24)     env0 = ffma2(p0, swe2[cp][k0], env0);
                if (k0 + 1 <= 24) env0 = ffma2(p1, swe2[cp][k0 + 1], env0);
                if (k0 >= 1)      env1 = ffma2(p0, swe2[cp][k0 - 1], env1);
                if (k0 <= 24)     env1 = ffma2(p1, swe2[cp][k0], env1);
            }
            F4U vr; vr.v = *(const float4*)&sxr2[cp * NWIN + j0 + 12];
            ull xraw0 = vr.u[0], xraw1 = vr.u[1];
            ull bur0 = 0ULL, bur1 = 0ULL;
            #pragma unroll
            for (int u = 0; u < 5; u++) {
                F4U v; v.v = *(const float4*)&dx[j0 + 8 + 2 * u];
                const int k0 = 2 * u;
                if (k0 <= 8)     bur0 = ffma2(v.u[0], swb2[cp][k0], bur0);
                if (k0 + 1 <= 8) bur0 = ffma2(v.u[1], swb2[cp][k0 + 1], bur0);
                if (k0 >= 1)     bur1 = ffma2(v.u[0], swb2[cp][k0 - 1], bur1);
                if (k0 <= 8)     bur1 = ffma2(v.u[1], swb2[cp][k0], bur1);
            }
            ull xm0 = ffma2(env0, C09P, ffma2(bur0, C06P, mul2(xraw0, C02P)));
            ull xm1 = ffma2(env1, C09P, ffma2(bur1, C06P, mul2(xraw1, C02P)));
            #pragma unroll
            for (int m = 0; m < MS; m++) {
                ull w = sWsyn2[cp][m];
                accm[m][0] = ffma2(xm0, w, accm[m][0]);
                accm[m][1] = ffma2(xm1, w, accm[m][1]);
            }
        }
        #pragma unroll
        for (int p = 0; p < 2; p++) {
            int j  = j0 + p;
            int tp = t0 - 4 + j;
            bool valid = (tp >= 0 && tp < Tt);
            float s0[MS];
            #pragma unroll
            for (int m = 0; m < MS; m++) {
                UF2 u; u.u = accm[m][p];
                s0[m] = valid ? (u.f.x + u.f.y) : 0.f;
            }
            sS02[j] = pack2(s0[0], s0[1]);
            sS02[NS0 + j] = pack2(s0[2], s0[3]);
        }
    }
    __syncthreads();

    // ---- phase C: rolling dwconv9+gelu, pointwise+gelu, write sX (k'-packed) ----
    if (tid < 250) {
        const int i0 = tid * 2;
        float S1[2][MS];
        #pragma unroll
        for (int p2 = 0; p2 < 2; p2++) {
            const ull* s0p = sS02 + p2 * NS0;
            ull a0 = 0ULL, a1 = 0ULL;
            #pragma unroll
            for (int u = 0; u < 5; u++) {
                F4U v; v.v = *(const float4*)&s0p[i0 + 2 * u];
                const int k0 = 2 * u;
                if (k0 <= 8)     a0 = ffma2(v.u[0], swd2[p2][k0], a0);
                if (k0 + 1 <= 8) a0 = ffma2(v.u[1], swd2[p2][k0 + 1], a0);
                if (k0 >= 1)     a1 = ffma2(v.u[0], swd2[p2][k0 - 1], a1);
                if (k0 <= 8)     a1 = ffma2(v.u[1], swd2[p2][k0], a1);
            }
            UF2 u0, u1; u0.u = a0; u1.u = a1;
            S1[0][2 * p2]     = gelu_exact(u0.f.x);
            S1[0][2 * p2 + 1] = gelu_exact(u0.f.y);
            S1[1][2 * p2]     = gelu_exact(u1.f.x);
            S1[1][2 * p2 + 1] = gelu_exact(u1.f.y);
        }
        #pragma unroll
        for (int pos = 0; pos < 2; pos++) {
            int i = i0 + pos;
            uchar4 mk = smask[i];
            float mf0 = (float)mk.x, mf1 = (float)mk.y, mf2 = (float)mk.z, mf3 = (float)mk.w;
            int l = i / PP, p = i - l * PP;
            float smsum = 0.f;
            H4U Hh, Hl;
            #pragma unroll
            for (int o = 0; o < MS; o++) {
                float a  = sPW[o][0] * S1[pos][0] + sPW[o][1] * S1[pos][1]
                         + sPW[o][2] * S1[pos][2] + sPW[o][3] * S1[pos][3];
                float s2 = gelu_exact(a);
                float sm = sW[o][0] * mf0 + sW[o][1] * mf1 + sW[o][2] * mf2 + sW[o][3] * mf3;
                sm = fminf(fmaxf(sm, 0.f), 1.f);
                smsum += sm;
                float v = s2 * sm;
                __half h = __float2half_rn(v);
                Hh.h[o] = h;
                Hl.h[o] = __float2half_rn(v - __half2float(h));
            }
            ((ull*)sXh)[l * (XST / 4) + p] = Hh.u;
            ((ull*)sXl)[l * (XST / 4) + p] = Hl.u;
            smt[i] = (smsum > 0.f) ? 1 : 0;
        }
    }
    __syncthreads();

    // ---- m_patch ----
    if (tid < RPT) {
        int s = 0;
        #pragma unroll
        for (int p = 0; p < PP; p++) s += smt[tid * PP + p];
        out[(size_t)HSIZE + Row0 + tid] = (s >= 3) ? 1.f : 0.f;
    }

    // ---- HMMA mainloop: 8 warps = 2 rg x 4 nq; both passes per warp ----
    const int rg = wid >> 2;           // row-group (m16): rows rg*16..rg*16+15
    const int nq = wid & 3;            // n-quarter (5 nn chunks)
    const int r0 = lane >> 2;

    float acc[5][4];
    #pragma unroll
    for (int n = 0; n < 5; n++)
        #pragma unroll
        for (int j = 0; j < 4; j++) acc[n][j] = 0.f;

    {
        const uint2* gbf = (const uint2*)g_bfrag;
        const int rowb = rg * 16;
        #pragma unroll
        for (int kc = 0; kc < NKC; kc++) {
            int c0 = kc * 16 + (lane & 3) * 2;
            unsigned h0 = *(const unsigned*)&sXh[(rowb + r0) * XST + c0];
            unsigned h1 = *(const unsigned*)&sXh[(rowb + r0 + 8) * XST + c0];
            unsigned h2 = *(const unsigned*)&sXh[(rowb + r0) * XST + c0 + 8];
            unsigned h3 = *(const unsigned*)&sXh[(rowb + r0 + 8) * XST + c0 + 8];
            unsigned l0 = *(const unsigned*)&sXl[(rowb + r0) * XST + c0];
            unsigned l1 = *(const unsigned*)&sXl[(rowb + r0 + 8) * XST + c0];
            unsigned l2 = *(const unsigned*)&sXl[(rowb + r0) * XST + c0 + 8];
            unsigned l3 = *(const unsigned*)&sXl[(rowb + r0 + 8) * XST + c0 + 8];
            #pragma unroll
            for (int n = 0; n < 5; n++) {
                int nn = nq * 5 + n;
                uint2 bf = gbf[(kc * NNC + nn) * 32 + lane];
                hmma16816(acc[n][0], acc[n][1], acc[n][2], acc[n][3],
                          h0, h1, h2, h3, bf.x, bf.y);
                hmma16816(acc[n][0], acc[n][1], acc[n][2], acc[n][3],
                          l0, l1, l2, l3, bf.x, bf.y);
            }
        }
    }

    // ---- LN partial moments: quad reduce within warp ----
    {
        float s0 = 0.f, q0 = 0.f, s1 = 0.f, q1 = 0.f;
        #pragma unroll
        for (int n = 0; n < 5; n++) {
            s0 += acc[n][0] + acc[n][1];
            q0 += acc[n][0] * acc[n][0] + acc[n][1] * acc[n][1];
            s1 += acc[n][2] + acc[n][3];
            q1 += acc[n][2] * acc[n][2] + acc[n][3] * acc[n][3];
        }
        #pragma unroll
        for (int off = 1; off <= 2; off <<= 1) {
            s0 += __shfl_xor_sync(0xFFFFFFFFu, s0, off);
            q0 += __shfl_xor_sync(0xFFFFFFFFu, q0, off);
            s1 += __shfl_xor_sync(0xFFFFFFFFu, s1, off);
            q1 += __shfl_xor_sync(0xFFFFFFFFu, q1, off);
        }
        if ((lane & 3) == 0) {
            sSum[nq][rg * 16 + r0]     = s0; sSq[nq][rg * 16 + r0]     = q0;
            sSum[nq][rg * 16 + r0 + 8] = s1; sSq[nq][rg * 16 + r0 + 8] = q1;
        }
    }
    __syncthreads();

    if (tid < RPT) {
        float s = sSum[0][tid] + sSum[1][tid] + sSum[2][tid] + sSum[3][tid];
        float q = sSq[0][tid] + sSq[1][tid] + sSq[2][tid] + sSq[3][tid];
        float mu  = s * (1.0f / Dd);
        float var = q * (1.0f / Dd) - mu * mu;
        sMu[tid] = mu;
        sRs[tid] = rsqrtf(var + 1e-5f);
    }
    __syncthreads();

    // ---- normalize + store ----
    {
        int rA = rg * 16 + r0;
        int rB = rA + 8;
        bool hasA = (rA < RPT);
        bool hasB = (rB < RPT);
        float muA = hasA ? sMu[rA] : 0.f, rsA = hasA ? sRs[rA] : 0.f;
        float muB = hasB ? sMu[rB] : 0.f, rsB = hasB ? sRs[rB] : 0.f;
        float* outA = out + (size_t)(Row0 + rA) * Dd;
        float* outB = out + (size_t)(Row0 + rB) * Dd;
        #pragma unroll
        for (int n = 0; n < 5; n++) {
            int col = (nq * 5 + n) * 8 + (lane & 3) * 2;
            float2 gm = *(const float2*)&sG[col];
            float2 bt = *(const float2*)&sBt[col];
            if (hasA) {
                float2 v;
                v.x = (acc[n][0] - muA) * rsA * gm.x + bt.x;
                v.y = (acc[n][1] - muA) * rsA * gm.y + bt.y;
                *(float2*)(outA + col) = v;
            }
            if (hasB) {
                float2 v;
                v.x = (acc[n][2] - muB) * rsB * gm.x + bt.x;
                v.y = (acc[n][3] - muB) * rsB * gm.y + bt.y;
                *(float2*)(outB + col) = v;
            }
        }
    }
}

// ---------------------------------------------------------------------------
extern "C" void kernel_launch(void* const* d_in, const int* in_sizes, int n_in,
                              void* d_out, int out_size)
{
    const float* X      = (const float*)d_in[0];
    const float* M      = (const float*)d_in[1];
    const float* w_env  = (const float*)d_in[2];
    const float* w_bur  = (const float*)d_in[3];
    const float* syn    = (const float*)d_in[4];
    const float* w_dw   = (const float*)d_in[5];
    const float* w_pw   = (const float*)d_in[6];
    const float* w_proj = (const float*)d_in[7];
    const float* gamma  = (const float*)d_in[8];
    const float* beta   = (const float*)d_in[9];
    float* out = (float*)d_out;

    cudaFuncSetAttribute(kernelF, cudaFuncAttributeMaxDynamicSharedMemorySize, DYN_SMEM);

    kernelW<<<(BFRAG_U32 + 255) / 256, 256>>>(w_proj);
    dim3 gF(NT, Bb);
    kernelF<<<gF, 256, DYN_SMEM>>>(X, M, w_env, w_bur, syn, w_dw, w_pw,
                                   gamma, beta, out);
}